// round 1
// baseline (speedup 1.0000x reference)
#include <cuda_runtime.h>
#include <cstdint>

#define NN 100000
#define EE 1600000

// ---------------- scratch (static device arrays; no allocation) ----------------
__device__ float g_deg[NN];
__device__ float g_dinv[NN];
__device__ int   g_cnt[NN];
__device__ int   g_rowptr[NN + 1];
__device__ int   g_fill[NN];
__device__ int   g_src_s[EE];    // edge sources in CSR(dst) order
__device__ float g_norm_s[EE];   // dinv[src]*w in CSR(dst) order
__device__ float g_h1[(size_t)NN * 128];
__device__ float g_a1[(size_t)NN * 128];
__device__ float g_h2[(size_t)NN * 64];

// ---------------- degree + histogram ----------------
__global__ void zero_kernel(int n) {
    int i = blockIdx.x * blockDim.x + threadIdx.x;
    if (i < n) { g_deg[i] = 0.0f; g_cnt[i] = 0; }
}

__global__ void deg_hist_kernel(const int* __restrict__ dst,
                                const float* __restrict__ w, int E) {
    int e = blockIdx.x * blockDim.x + threadIdx.x;
    if (e < E) {
        int d = dst[e];
        atomicAdd(&g_deg[d], w[e]);
        atomicAdd(&g_cnt[d], 1);
    }
}

__global__ void dinv_kernel(int n) {
    int i = blockIdx.x * blockDim.x + threadIdx.x;
    if (i < n) g_dinv[i] = rsqrtf(g_deg[i] + 1.0f);  // +1 = self loop weight
}

// ---------------- single-block exclusive scan over g_cnt -> g_rowptr, g_fill ----
__global__ void scan_kernel(int n) {
    __shared__ int sh[1024];
    __shared__ int s_carry;
    int tid = threadIdx.x;
    if (tid == 0) s_carry = 0;
    __syncthreads();
    for (int base = 0; base < n; base += 1024) {
        int i = base + tid;
        int v = (i < n) ? g_cnt[i] : 0;
        sh[tid] = v;
        __syncthreads();
        #pragma unroll
        for (int off = 1; off < 1024; off <<= 1) {
            int t = (tid >= off) ? sh[tid - off] : 0;
            __syncthreads();
            sh[tid] += t;
            __syncthreads();
        }
        int carry = s_carry;
        int excl = carry + sh[tid] - v;
        if (i < n) { g_rowptr[i] = excl; g_fill[i] = excl; }
        __syncthreads();
        if (tid == 1023) s_carry = carry + sh[1023];
        __syncthreads();
    }
    if (tid == 0) g_rowptr[n] = s_carry;
}

// ---------------- scatter edges into CSR order, precompute dinv[s]*w ----------
__global__ void scatter_kernel(const int* __restrict__ src,
                               const int* __restrict__ dst,
                               const float* __restrict__ w, int E) {
    int e = blockIdx.x * blockDim.x + threadIdx.x;
    if (e < E) {
        int d = dst[e];
        int s = src[e];
        int pos = atomicAdd(&g_fill[d], 1);
        g_src_s[pos]  = s;
        g_norm_s[pos] = g_dinv[s] * w[e];
    }
}

// ---------------- dense GEMM: C[nrows,OUTD] = A[nrows,128] @ W[128,OUTD] ------
template <int OUTD>
__device__ __forceinline__ void gemm_body(const float* __restrict__ A,
                                          const float* __restrict__ W,
                                          float* __restrict__ C, int nrows) {
    constexpr int KB  = 16;
    constexpr int CT  = OUTD / 4;   // col-thread count (32 or 16)
    constexpr int RT  = 256 / CT;   // row-thread count (8 or 16)
    constexpr int RPT = 64 / RT;    // rows per thread (8 or 4)
    __shared__ float As[64 * KB];
    __shared__ float Ws[KB * OUTD];

    int tid  = threadIdx.x;
    int row0 = blockIdx.x * 64;
    int tc = tid % CT;
    int tr = tid / CT;

    float acc[RPT][4];
    #pragma unroll
    for (int i = 0; i < RPT; i++)
        { acc[i][0] = 0.f; acc[i][1] = 0.f; acc[i][2] = 0.f; acc[i][3] = 0.f; }

    for (int k0 = 0; k0 < 128; k0 += KB) {
        // load A tile: 64 rows x 16 k
        {
            int r = tid >> 2, q = tid & 3;
            int grow = row0 + r;
            float4 v = (grow < nrows)
                ? *(const float4*)&A[(size_t)grow * 128 + k0 + q * 4]
                : make_float4(0.f, 0.f, 0.f, 0.f);
            *(float4*)&As[r * KB + q * 4] = v;
        }
        // load W tile: 16 x OUTD
        {
            constexpr int TOT4 = KB * OUTD / 4;
            #pragma unroll
            for (int i = tid; i < TOT4; i += 256) {
                int kk = i / (OUTD / 4), c4 = i % (OUTD / 4);
                *(float4*)&Ws[kk * OUTD + c4 * 4] =
                    *(const float4*)&W[(size_t)(k0 + kk) * OUTD + c4 * 4];
            }
        }
        __syncthreads();
        #pragma unroll
        for (int kk = 0; kk < KB; kk++) {
            float4 b = *(float4*)&Ws[kk * OUTD + tc * 4];
            #pragma unroll
            for (int i = 0; i < RPT; i++) {
                float a = As[(tr * RPT + i) * KB + kk];
                acc[i][0] += a * b.x;
                acc[i][1] += a * b.y;
                acc[i][2] += a * b.z;
                acc[i][3] += a * b.w;
            }
        }
        __syncthreads();
    }
    #pragma unroll
    for (int i = 0; i < RPT; i++) {
        int grow = row0 + tr * RPT + i;
        if (grow < nrows) {
            float4 v = make_float4(acc[i][0], acc[i][1], acc[i][2], acc[i][3]);
            *(float4*)&C[(size_t)grow * OUTD + tc * 4] = v;
        }
    }
}

__global__ void gemm1_kernel(const float* __restrict__ x,
                             const float* __restrict__ W1, int n) {
    gemm_body<128>(x, W1, g_h1, n);
}
__global__ void gemm2_kernel(const float* __restrict__ W2, int n) {
    gemm_body<64>(g_a1, W2, g_h2, n);
}

// ---------------- CSR aggregation: one warp per node, no atomics -------------
template <int D, bool RELU>
__device__ __forceinline__ void agg_body(const float* __restrict__ h,
                                         const float* __restrict__ bias,
                                         float* __restrict__ out, int n) {
    constexpr int V = D / 32;       // 4 (D=128) or 2 (D=64)
    int gwarp = (blockIdx.x * blockDim.x + threadIdx.x) >> 5;
    int lane  = threadIdx.x & 31;
    if (gwarp >= n) return;
    int node = gwarp;

    float dv = g_dinv[node];
    float acc[V];
    #pragma unroll
    for (int i = 0; i < V; i++) acc[i] = 0.f;

    int beg = g_rowptr[node];
    int end = g_rowptr[node + 1];
    for (int e = beg; e < end; e++) {
        int   s  = g_src_s[e];
        float nm = g_norm_s[e] * dv;
        const float* hp = &h[(size_t)s * D + lane * V];
        if (V == 4) {
            float4 v = *(const float4*)hp;
            acc[0] += nm * v.x; acc[1] += nm * v.y;
            acc[2] += nm * v.z; acc[3] += nm * v.w;
        } else {
            float2 v = *(const float2*)hp;
            acc[0] += nm * v.x; acc[1] += nm * v.y;
        }
    }
    // self loop: norm = dinv[n]^2
    {
        float nm = dv * dv;
        const float* hp = &h[(size_t)node * D + lane * V];
        if (V == 4) {
            float4 v = *(const float4*)hp;
            acc[0] += nm * v.x; acc[1] += nm * v.y;
            acc[2] += nm * v.z; acc[3] += nm * v.w;
        } else {
            float2 v = *(const float2*)hp;
            acc[0] += nm * v.x; acc[1] += nm * v.y;
        }
    }
    float* op = &out[(size_t)node * D + lane * V];
    if (V == 4) {
        float4 r;
        r.x = acc[0] + bias[lane * 4 + 0];
        r.y = acc[1] + bias[lane * 4 + 1];
        r.z = acc[2] + bias[lane * 4 + 2];
        r.w = acc[3] + bias[lane * 4 + 3];
        if (RELU) {
            r.x = fmaxf(r.x, 0.f); r.y = fmaxf(r.y, 0.f);
            r.z = fmaxf(r.z, 0.f); r.w = fmaxf(r.w, 0.f);
        }
        *(float4*)op = r;
    } else {
        float2 r;
        r.x = acc[0] + bias[lane * 2 + 0];
        r.y = acc[1] + bias[lane * 2 + 1];
        if (RELU) { r.x = fmaxf(r.x, 0.f); r.y = fmaxf(r.y, 0.f); }
        *(float2*)op = r;
    }
}

__global__ void agg1_kernel(const float* __restrict__ b1, int n) {
    agg_body<128, true>(g_h1, b1, g_a1, n);
}
__global__ void agg2_kernel(const float* __restrict__ b2,
                            float* __restrict__ out, int n) {
    agg_body<64, false>(g_h2, b2, out, n);
}

// ---------------- launch ----------------
extern "C" void kernel_launch(void* const* d_in, const int* in_sizes, int n_in,
                              void* d_out, int out_size) {
    const float* x  = (const float*)d_in[0];
    const int*   ei = (const int*)  d_in[1];
    const float* w  = (const float*)d_in[2];
    const float* W1 = (const float*)d_in[3];
    const float* b1 = (const float*)d_in[4];
    const float* W2 = (const float*)d_in[5];
    const float* b2 = (const float*)d_in[6];
    float* out = (float*)d_out;

    int E = in_sizes[1] / 2;
    int n = in_sizes[0] / 128;
    const int* src = ei;
    const int* dst = ei + E;

    int nb_n = (n + 255) / 256;
    int nb_e = (E + 255) / 256;

    zero_kernel<<<nb_n, 256>>>(n);
    deg_hist_kernel<<<nb_e, 256>>>(dst, w, E);
    dinv_kernel<<<nb_n, 256>>>(n);
    scan_kernel<<<1, 1024>>>(n);
    scatter_kernel<<<nb_e, 256>>>(src, dst, w, E);

    int nb_g = (n + 63) / 64;
    int nb_a = (n + 7) / 8;   // 8 warps per block, 1 warp per node

    gemm1_kernel<<<nb_g, 256>>>(x, W1, n);
    agg1_kernel<<<nb_a, 256>>>(b1, n);
    gemm2_kernel<<<nb_g, 256>>>(W2, n);
    agg2_kernel<<<nb_a, 256>>>(b2, out, n);
}

// round 2
// speedup vs baseline: 1.4510x; 1.4510x over previous
#include <cuda_runtime.h>
#include <cstdint>

#define NN 100000
#define EE 1600000
#define SCAN_B 1024
#define NBLK ((NN + SCAN_B - 1) / SCAN_B)   // 98

// ---------------- scratch (static device arrays; no allocation) ----------------
__device__ float g_deg[NN];
__device__ float g_dinv[NN];
__device__ int   g_cnt[NN];
__device__ int   g_rowptr[NN + 1];
__device__ int   g_fill[NN];
__device__ int   g_blksum[NBLK];
__device__ int   g_blkoff[NBLK + 1];
__device__ int   g_src_s[EE];    // edge sources in CSR(dst) order
__device__ float g_norm_s[EE];   // dinv[src]*w in CSR(dst) order
__device__ float g_h1[(size_t)NN * 128];
__device__ float g_a1[(size_t)NN * 128];
__device__ float g_h2[(size_t)NN * 64];

// ---------------- degree + histogram ----------------
__global__ void zero_kernel(int n) {
    int i = blockIdx.x * blockDim.x + threadIdx.x;
    if (i < n) { g_deg[i] = 0.0f; g_cnt[i] = 0; }
}

__global__ void deg_hist_kernel(const int* __restrict__ dst,
                                const float* __restrict__ w, int E) {
    int e = blockIdx.x * blockDim.x + threadIdx.x;
    if (e < E) {
        int d = dst[e];
        atomicAdd(&g_deg[d], w[e]);
        atomicAdd(&g_cnt[d], 1);
    }
}

__global__ void dinv_kernel(int n) {
    int i = blockIdx.x * blockDim.x + threadIdx.x;
    if (i < n) g_dinv[i] = rsqrtf(g_deg[i] + 1.0f);  // +1 = self loop weight
}

// ---------------- hierarchical scan: local pass ----------------
__global__ void scan_local_kernel(int n) {
    __shared__ int warp_sums[32];
    int tid  = threadIdx.x;
    int i    = blockIdx.x * SCAN_B + tid;
    int lane = tid & 31;
    int wid  = tid >> 5;

    int v = (i < n) ? g_cnt[i] : 0;

    // warp inclusive scan
    int s = v;
    #pragma unroll
    for (int off = 1; off < 32; off <<= 1) {
        int t = __shfl_up_sync(0xffffffffu, s, off);
        if (lane >= off) s += t;
    }
    if (lane == 31) warp_sums[wid] = s;
    __syncthreads();

    // warp 0 scans the 32 warp sums
    if (wid == 0) {
        int ws = warp_sums[lane];
        int sw = ws;
        #pragma unroll
        for (int off = 1; off < 32; off <<= 1) {
            int t = __shfl_up_sync(0xffffffffu, sw, off);
            if (lane >= off) sw += t;
        }
        warp_sums[lane] = sw - ws;  // exclusive
        if (lane == 31 && blockIdx.x < NBLK) g_blksum[blockIdx.x] = sw;
    }
    __syncthreads();

    int excl = s - v + warp_sums[wid];   // block-local exclusive
    if (i < n) g_rowptr[i] = excl;
}

// ---------------- hierarchical scan: block-sum pass (1 block) ----------------
__global__ void scan_blocks_kernel(int n) {
    // NBLK = 98 <= 128; scan with 4 warps + smem
    __shared__ int sh[128];
    int tid = threadIdx.x;  // 128 threads
    int v = (tid < NBLK) ? g_blksum[tid] : 0;
    sh[tid] = v;
    __syncthreads();
    #pragma unroll
    for (int off = 1; off < 128; off <<= 1) {
        int t = (tid >= off) ? sh[tid - off] : 0;
        __syncthreads();
        sh[tid] += t;
        __syncthreads();
    }
    if (tid < NBLK) g_blkoff[tid] = sh[tid] - v;   // exclusive
    if (tid == 127) g_rowptr[n] = sh[127];          // total
}

// ---------------- hierarchical scan: apply offsets ----------------
__global__ void scan_apply_kernel(int n) {
    int i = blockIdx.x * blockDim.x + threadIdx.x;
    if (i < n) {
        int r = g_rowptr[i] + g_blkoff[i >> 10];
        g_rowptr[i] = r;
        g_fill[i]   = r;
    }
}

// ---------------- scatter edges into CSR order, precompute dinv[s]*w ----------
__global__ void scatter_kernel(const int* __restrict__ src,
                               const int* __restrict__ dst,
                               const float* __restrict__ w, int E) {
    int e = blockIdx.x * blockDim.x + threadIdx.x;
    if (e < E) {
        int d = dst[e];
        int s = src[e];
        int pos = atomicAdd(&g_fill[d], 1);
        g_src_s[pos]  = s;
        g_norm_s[pos] = g_dinv[s] * w[e];
    }
}

// ---------------- dense GEMM: C[nrows,OUTD] = A[nrows,128] @ W[128,OUTD] ------
template <int OUTD>
__device__ __forceinline__ void gemm_body(const float* __restrict__ A,
                                          const float* __restrict__ W,
                                          float* __restrict__ C, int nrows) {
    constexpr int KB  = 16;
    constexpr int CT  = OUTD / 4;   // col-thread count (32 or 16)
    constexpr int RT  = 256 / CT;   // row-thread count (8 or 16)
    constexpr int RPT = 64 / RT;    // rows per thread (8 or 4)
    __shared__ float As[64 * KB];
    __shared__ float Ws[KB * OUTD];

    int tid  = threadIdx.x;
    int row0 = blockIdx.x * 64;
    int tc = tid % CT;
    int tr = tid / CT;

    float acc[RPT][4];
    #pragma unroll
    for (int i = 0; i < RPT; i++)
        { acc[i][0] = 0.f; acc[i][1] = 0.f; acc[i][2] = 0.f; acc[i][3] = 0.f; }

    for (int k0 = 0; k0 < 128; k0 += KB) {
        // load A tile: 64 rows x 16 k
        {
            int r = tid >> 2, q = tid & 3;
            int grow = row0 + r;
            float4 v = (grow < nrows)
                ? *(const float4*)&A[(size_t)grow * 128 + k0 + q * 4]
                : make_float4(0.f, 0.f, 0.f, 0.f);
            *(float4*)&As[r * KB + q * 4] = v;
        }
        // load W tile: 16 x OUTD
        {
            constexpr int TOT4 = KB * OUTD / 4;
            #pragma unroll
            for (int i = tid; i < TOT4; i += 256) {
                int kk = i / (OUTD / 4), c4 = i % (OUTD / 4);
                *(float4*)&Ws[kk * OUTD + c4 * 4] =
                    *(const float4*)&W[(size_t)(k0 + kk) * OUTD + c4 * 4];
            }
        }
        __syncthreads();
        #pragma unroll
        for (int kk = 0; kk < KB; kk++) {
            float4 b = *(float4*)&Ws[kk * OUTD + tc * 4];
            #pragma unroll
            for (int i = 0; i < RPT; i++) {
                float a = As[(tr * RPT + i) * KB + kk];
                acc[i][0] += a * b.x;
                acc[i][1] += a * b.y;
                acc[i][2] += a * b.z;
                acc[i][3] += a * b.w;
            }
        }
        __syncthreads();
    }
    #pragma unroll
    for (int i = 0; i < RPT; i++) {
        int grow = row0 + tr * RPT + i;
        if (grow < nrows) {
            float4 v = make_float4(acc[i][0], acc[i][1], acc[i][2], acc[i][3]);
            *(float4*)&C[(size_t)grow * OUTD + tc * 4] = v;
        }
    }
}

__global__ void gemm1_kernel(const float* __restrict__ x,
                             const float* __restrict__ W1, int n) {
    gemm_body<128>(x, W1, g_h1, n);
}
__global__ void gemm2_kernel(const float* __restrict__ W2, int n) {
    gemm_body<64>(g_a1, W2, g_h2, n);
}

// ---------------- CSR aggregation: one warp per node, no atomics -------------
template <int D, bool RELU>
__device__ __forceinline__ void agg_body(const float* __restrict__ h,
                                         const float* __restrict__ bias,
                                         float* __restrict__ out, int n) {
    constexpr int V = D / 32;       // 4 (D=128) or 2 (D=64)
    int gwarp = (blockIdx.x * blockDim.x + threadIdx.x) >> 5;
    int lane  = threadIdx.x & 31;
    if (gwarp >= n) return;
    int node = gwarp;

    float dv = g_dinv[node];
    float acc[V];
    #pragma unroll
    for (int i = 0; i < V; i++) acc[i] = 0.f;

    int beg = g_rowptr[node];
    int end = g_rowptr[node + 1];
    for (int e = beg; e < end; e++) {
        int   s  = g_src_s[e];
        float nm = g_norm_s[e] * dv;
        const float* hp = &h[(size_t)s * D + lane * V];
        if (V == 4) {
            float4 v = *(const float4*)hp;
            acc[0] += nm * v.x; acc[1] += nm * v.y;
            acc[2] += nm * v.z; acc[3] += nm * v.w;
        } else {
            float2 v = *(const float2*)hp;
            acc[0] += nm * v.x; acc[1] += nm * v.y;
        }
    }
    // self loop: norm = dinv[n]^2
    {
        float nm = dv * dv;
        const float* hp = &h[(size_t)node * D + lane * V];
        if (V == 4) {
            float4 v = *(const float4*)hp;
            acc[0] += nm * v.x; acc[1] += nm * v.y;
            acc[2] += nm * v.z; acc[3] += nm * v.w;
        } else {
            float2 v = *(const float2*)hp;
            acc[0] += nm * v.x; acc[1] += nm * v.y;
        }
    }
    float* op = &out[(size_t)node * D + lane * V];
    if (V == 4) {
        float4 r;
        r.x = acc[0] + bias[lane * 4 + 0];
        r.y = acc[1] + bias[lane * 4 + 1];
        r.z = acc[2] + bias[lane * 4 + 2];
        r.w = acc[3] + bias[lane * 4 + 3];
        if (RELU) {
            r.x = fmaxf(r.x, 0.f); r.y = fmaxf(r.y, 0.f);
            r.z = fmaxf(r.z, 0.f); r.w = fmaxf(r.w, 0.f);
        }
        *(float4*)op = r;
    } else {
        float2 r;
        r.x = acc[0] + bias[lane * 2 + 0];
        r.y = acc[1] + bias[lane * 2 + 1];
        if (RELU) { r.x = fmaxf(r.x, 0.f); r.y = fmaxf(r.y, 0.f); }
        *(float2*)op = r;
    }
}

__global__ void agg1_kernel(const float* __restrict__ b1, int n) {
    agg_body<128, true>(g_h1, b1, g_a1, n);
}
__global__ void agg2_kernel(const float* __restrict__ b2,
                            float* __restrict__ out, int n) {
    agg_body<64, false>(g_h2, b2, out, n);
}

// ---------------- launch ----------------
extern "C" void kernel_launch(void* const* d_in, const int* in_sizes, int n_in,
                              void* d_out, int out_size) {
    const float* x  = (const float*)d_in[0];
    const int*   ei = (const int*)  d_in[1];
    const float* w  = (const float*)d_in[2];
    const float* W1 = (const float*)d_in[3];
    const float* b1 = (const float*)d_in[4];
    const float* W2 = (const float*)d_in[5];
    const float* b2 = (const float*)d_in[6];
    float* out = (float*)d_out;

    int E = in_sizes[1] / 2;
    int n = in_sizes[0] / 128;
    const int* src = ei;
    const int* dst = ei + E;

    int nb_n = (n + 255) / 256;
    int nb_e = (E + 255) / 256;
    int nb_s = (n + SCAN_B - 1) / SCAN_B;

    zero_kernel<<<nb_n, 256>>>(n);
    deg_hist_kernel<<<nb_e, 256>>>(dst, w, E);
    dinv_kernel<<<nb_n, 256>>>(n);
    scan_local_kernel<<<nb_s, SCAN_B>>>(n);
    scan_blocks_kernel<<<1, 128>>>(n);
    scan_apply_kernel<<<nb_n, 256>>>(n);
    scatter_kernel<<<nb_e, 256>>>(src, dst, w, E);

    int nb_g = (n + 63) / 64;
    int nb_a = (n + 7) / 8;   // 8 warps per block, 1 warp per node

    gemm1_kernel<<<nb_g, 256>>>(x, W1, n);
    agg1_kernel<<<nb_a, 256>>>(b1, n);
    gemm2_kernel<<<nb_g, 256>>>(W2, n);
    agg2_kernel<<<nb_a, 256>>>(b2, out, n);
}